// round 7
// baseline (speedup 1.0000x reference)
#include <cuda_runtime.h>

// Problem constants
#define B_TOT    4096
#define T_STEPS  512
#define D_IN     6
#define H_DIM    32
#define NB       8                       // batch elements per warp
#define WARPS    4
#define NTHREADS (WARPS * 32)            // 128
#define BPB      (WARPS * NB)            // 32 batch per block
#define NBLOCKS  (B_TOT / BPB)           // 128
#define TCHUNK   32
#define NCHUNKS  (T_STEPS / TCHUNK)      // 16

// ---------------- SMEM layout (float units) ----------------
// whh0  : 0     .. 4096    [k][j] float4 gates (i,f,g,o)
// wih1  : 4096  .. 8192
// whh1  : 8192  .. 12288
// wih0  : 12288 .. 13056   [d][j] float4 gates
// b0s   : 13056 .. 13184   [j] float4
// b1s   : 13184 .. 13312
// hd0   : 13312 .. 15360   [warp][nb][k] float2 (h,h) duplicated
// hd1   : 15360 .. 17408
// xbuf  : 17408 .. 29696   [2][TCHUNK][BPB][6] floats
#define SMEM_FLOATS 29696
#define SMEM_BYTES  (SMEM_FLOATS * 4)    // 118784

__device__ __forceinline__ float sigm(float x) {
    return __fdividef(1.0f, 1.0f + __expf(-x));
}
__device__ __forceinline__ float tanh_(float x) {
    float a = fabsf(x);
    float e = __expf(-2.0f * a);
    float r = (1.0f - e) * __fdividef(1.0f, 1.0f + e);
    return copysignf(r, x);
}

// pack (v, v) into a b64 register
__device__ __forceinline__ unsigned long long pk2(float v) {
    unsigned long long r;
    unsigned u = __float_as_uint(v);
    asm("mov.b64 %0, {%1, %1};" : "=l"(r) : "r"(u));
    return r;
}
// unpack b64 -> (lo, hi) floats
__device__ __forceinline__ float2 upk(unsigned long long v) {
    unsigned lo, hi;
    asm("mov.b64 {%0, %1}, %2;" : "=r"(lo), "=r"(hi) : "l"(v));
    return make_float2(__uint_as_float(lo), __uint_as_float(hi));
}

// dual fp32 FMA: acc.(lo,hi) += wa.(lo,hi) * hb.(lo,hi)
#define FMA2(acc, wa, hb) \
    asm("fma.rn.f32x2 %0, %1, %2, %0;" : "+l"(acc) : "l"(wa), "l"(hb))

// 32-wide matvec, gate pairs (i,f)/(g,o):
//   WPTR: ulonglong2 SMEM ptr, entry (k*32 + j) = { (Wi,Wf), (Wg,Wo) }
//   HPTR: ulonglong2 SMEM ptr, entry (nb*16 + k2) = { (h_{2k2},h_{2k2}), (h_{2k2+1},h_{2k2+1}) }
#define MATVEC2(WPTR, HPTR)                                          \
    _Pragma("unroll 4")                                              \
    for (int k2 = 0; k2 < 16; ++k2) {                                \
        ulonglong2 w0 = (WPTR)[(2 * k2 + 0) * 32 + j];               \
        ulonglong2 w1 = (WPTR)[(2 * k2 + 1) * 32 + j];               \
        _Pragma("unroll")                                            \
        for (int nb = 0; nb < NB; ++nb) {                            \
            ulonglong2 hp = (HPTR)[nb * 16 + k2];                    \
            FMA2(aif[nb], w0.x, hp.x);                               \
            FMA2(ago[nb], w0.y, hp.x);                               \
            FMA2(aif[nb], w1.x, hp.y);                               \
            FMA2(ago[nb], w1.y, hp.y);                               \
        }                                                            \
    }

extern __shared__ float s[];

__global__ void __launch_bounds__(NTHREADS, 1) lstm2_ln_kernel(
    const float* __restrict__ x,
    const float* __restrict__ Wih0, const float* __restrict__ Whh0,
    const float* __restrict__ bih0, const float* __restrict__ bhh0,
    const float* __restrict__ Wih1, const float* __restrict__ Whh1,
    const float* __restrict__ bih1, const float* __restrict__ bhh1,
    const float* __restrict__ gamma, const float* __restrict__ beta,
    float* __restrict__ out)
{
    float* whh0 = s;
    float* wih1 = s + 4096;
    float* whh1 = s + 8192;
    float* wih0 = s + 12288;
    float* b0s  = s + 13056;
    float* b1s  = s + 13184;
    float* hd0  = s + 13312;
    float* hd1  = s + 15360;
    float* xb   = s + 17408;

    const int tid = threadIdx.x;

    // ---- kick off async staging of x chunk 0 ----
    {
        float* dst0 = xb;  // buf 0
        const float* src0 = x + (size_t)(blockIdx.x * BPB) * T_STEPS * D_IN;
        for (int c = tid; c < TCHUNK * BPB * 3; c += NTHREADS) {
            int t   = c / (BPB * 3);
            int rem = c - t * (BPB * 3);
            int b   = rem / 3;
            int p   = rem - b * 3;
            const float* src = src0 + ((size_t)b * T_STEPS + t) * D_IN + p * 2;
            float* dst = dst0 + (t * BPB + b) * 6 + p * 2;
            unsigned u = (unsigned)__cvta_generic_to_shared(dst);
            asm volatile("cp.async.ca.shared.global [%0], [%1], 8;" :: "r"(u), "l"(src));
        }
        asm volatile("cp.async.commit_group;" ::: "memory");
    }

    // ---- stage weights into SMEM, [k][j][gate i,f,g,o] ----
    {
        for (int idx = tid; idx < 4096; idx += NTHREADS) {
            int r = idx >> 5;            // row = g*32 + j
            int k = idx & 31;
            int g = r >> 5, jj = r & 31;
            int dst = (k * 32 + jj) * 4 + g;
            whh0[dst] = Whh0[idx];
            wih1[dst] = Wih1[idx];
            whh1[dst] = Whh1[idx];
        }
        for (int idx = tid; idx < 128 * D_IN; idx += NTHREADS) {
            int r = idx / D_IN;
            int d = idx - r * D_IN;
            int g = r >> 5, jj = r & 31;
            wih0[(d * 32 + jj) * 4 + g] = Wih0[idx];
        }
        if (tid < 128) {
            int g = tid >> 5, jj = tid & 31;
            b0s[jj * 4 + g] = bih0[tid] + bhh0[tid];
            b1s[jj * 4 + g] = bih1[tid] + bhh1[tid];
        }
        for (int idx = tid; idx < 4096; idx += NTHREADS) hd0[idx] = 0.0f;  // hd0+hd1
    }
    asm volatile("cp.async.wait_group 0;" ::: "memory");
    __syncthreads();

    const int warp  = tid >> 5;
    const int j     = tid & 31;
    const int bbase = (blockIdx.x * WARPS + warp) * NB;

    const ulonglong2 bias0 = ((const ulonglong2*)b0s)[j];
    const ulonglong2 bias1 = ((const ulonglong2*)b1s)[j];
    const ulonglong2* whh0u = (const ulonglong2*)whh0;
    const ulonglong2* wih1u = (const ulonglong2*)wih1;
    const ulonglong2* whh1u = (const ulonglong2*)whh1;
    const ulonglong2* wih0u = (const ulonglong2*)wih0;

    float2* myhd0s = (float2*)(hd0 + warp * NB * 64);   // [nb][k] float2
    float2* myhd1s = (float2*)(hd1 + warp * NB * 64);
    const ulonglong2* myhd0 = (const ulonglong2*)myhd0s;  // [nb*16 + k2]
    const ulonglong2* myhd1 = (const ulonglong2*)myhd1s;

    float c0[NB], c1[NB], h1[NB];
    #pragma unroll
    for (int nb = 0; nb < NB; ++nb) { c0[nb] = 0.f; c1[nb] = 0.f; h1[nb] = 0.f; }

    for (int ch = 0; ch < NCHUNKS; ++ch) {
        // prefetch next chunk into the other buffer
        if (ch + 1 < NCHUNKS) {
            float* dst0 = xb + ((ch + 1) & 1) * (TCHUNK * BPB * 6);
            const float* src0 = x + ((size_t)(blockIdx.x * BPB) * T_STEPS
                                     + (size_t)(ch + 1) * TCHUNK) * D_IN;
            for (int c = tid; c < TCHUNK * BPB * 3; c += NTHREADS) {
                int t   = c / (BPB * 3);
                int rem = c - t * (BPB * 3);
                int b   = rem / 3;
                int p   = rem - b * 3;
                const float* src = src0 + ((size_t)b * T_STEPS + t) * D_IN + p * 2;
                float* dst = dst0 + (t * BPB + b) * 6 + p * 2;
                unsigned u = (unsigned)__cvta_generic_to_shared(dst);
                asm volatile("cp.async.ca.shared.global [%0], [%1], 8;" :: "r"(u), "l"(src));
            }
            asm volatile("cp.async.commit_group;" ::: "memory");
        }

        const float* xc = xb + (ch & 1) * (TCHUNK * BPB * 6) + warp * NB * 6;

        for (int tl = 0; tl < TCHUNK; ++tl) {
            const float* xt = xc + tl * (BPB * 6);

            unsigned long long aif[NB], ago[NB];

            // ================= Layer 0 =================
            #pragma unroll
            for (int nb = 0; nb < NB; ++nb) { aif[nb] = bias0.x; ago[nb] = bias0.y; }

            #pragma unroll
            for (int d = 0; d < D_IN; ++d) {
                ulonglong2 wd = wih0u[d * 32 + j];
                #pragma unroll
                for (int nb = 0; nb < NB; ++nb) {
                    unsigned long long xp = pk2(xt[nb * 6 + d]);
                    FMA2(aif[nb], wd.x, xp);
                    FMA2(ago[nb], wd.y, xp);
                }
            }
            MATVEC2(whh0u, myhd0)

            __syncwarp();
            #pragma unroll
            for (int nb = 0; nb < NB; ++nb) {
                float2 gif = upk(aif[nb]);
                float2 ggo = upk(ago[nb]);
                float ii = sigm(gif.x);
                float ff = sigm(gif.y);
                float gg = tanh_(ggo.x);
                float oo = sigm(ggo.y);
                c0[nb] = fmaf(ff, c0[nb], ii * gg);
                float h = oo * tanh_(c0[nb]);
                myhd0s[nb * 32 + j] = make_float2(h, h);
            }
            __syncwarp();

            // ================= Layer 1 =================
            #pragma unroll
            for (int nb = 0; nb < NB; ++nb) { aif[nb] = bias1.x; ago[nb] = bias1.y; }

            MATVEC2(wih1u, myhd0)   // input = fresh h0
            MATVEC2(whh1u, myhd1)   // recurrent = previous h1

            __syncwarp();
            #pragma unroll
            for (int nb = 0; nb < NB; ++nb) {
                float2 gif = upk(aif[nb]);
                float2 ggo = upk(ago[nb]);
                float ii = sigm(gif.x);
                float ff = sigm(gif.y);
                float gg = tanh_(ggo.x);
                float oo = sigm(ggo.y);
                c1[nb] = fmaf(ff, c1[nb], ii * gg);
                h1[nb] = oo * tanh_(c1[nb]);
                myhd1s[nb * 32 + j] = make_float2(h1[nb], h1[nb]);
            }
            __syncwarp();
        }

        asm volatile("cp.async.wait_group 0;" ::: "memory");
        __syncthreads();
    }

    // ---- LayerNorm over last h1 (across the 32 lanes) ----
    const float gj = gamma[j];
    const float bj = beta[j];
    #pragma unroll
    for (int nb = 0; nb < NB; ++nb) {
        float v = h1[nb];
        float ssum = v;
        #pragma unroll
        for (int o = 16; o > 0; o >>= 1) ssum += __shfl_xor_sync(0xffffffffu, ssum, o);
        float mean = ssum * (1.0f / 32.0f);
        float dv = v - mean;
        float q = dv * dv;
        #pragma unroll
        for (int o = 16; o > 0; o >>= 1) q += __shfl_xor_sync(0xffffffffu, q, o);
        float var = q * (1.0f / 32.0f);
        float inv = rsqrtf(var + 1e-5f);
        out[(size_t)(bbase + nb) * H_DIM + j] = fmaf(dv * inv, gj, bj);
    }
}

extern "C" void kernel_launch(void* const* d_in, const int* in_sizes, int n_in,
                              void* d_out, int out_size)
{
    const float* x     = (const float*)d_in[0];
    const float* Wih0  = (const float*)d_in[1];
    const float* Whh0  = (const float*)d_in[2];
    const float* bih0  = (const float*)d_in[3];
    const float* bhh0  = (const float*)d_in[4];
    const float* Wih1  = (const float*)d_in[5];
    const float* Whh1  = (const float*)d_in[6];
    const float* bih1  = (const float*)d_in[7];
    const float* bhh1  = (const float*)d_in[8];
    const float* gamma = (const float*)d_in[9];
    const float* beta  = (const float*)d_in[10];
    float* out = (float*)d_out;

    static int attr_set = 0;
    if (!attr_set) {
        cudaFuncSetAttribute(lstm2_ln_kernel,
                             cudaFuncAttributeMaxDynamicSharedMemorySize, SMEM_BYTES);
        attr_set = 1;
    }

    lstm2_ln_kernel<<<NBLOCKS, NTHREADS, SMEM_BYTES>>>(
        x, Wih0, Whh0, bih0, bhh0, Wih1, Whh1, bih1, bhh1, gamma, beta, out);
}